// round 10
// baseline (speedup 1.0000x reference)
#include <cuda_runtime.h>
#include <math.h>

// ---------------------------------------------------------------------------
// DeformableAttention — fp32, double-buffered SGEMM (BM=BN=128, BK=16)
// with cp.async for the W-tile path. Inputs identified by element count
// (robust to whether scalars h/w are materialized as inputs).
//   B=8, Q=2048, D=256, HW=100*100, heads=8, points=4, Dh=32
// Stages:
//   1. values  = input_flatten @ W_val  + b_val      [80000,256]  (sgemm128)
//   2. offsets = query @ W_off + b_off               [16384,64]   (gemm64)
//   3. attn    = query @ W_attn + b_attn             [16384,32]   (gemm64)
//   4. bilinear sampling + softmax-weighted head sum [16384,256]
//   5. out     = heads @ W_out + b_out               [16384,256]  (sgemm128)
// ---------------------------------------------------------------------------

#define NH   8
#define NP   4
#define DH   32
#define DD   256
#define BB   8
#define QQ   2048
#define IMH  100
#define IMW  100
#define HWSZ (IMH * IMW)
#define BQ   (BB * QQ)

// Scratch (device globals — no allocations allowed)
__device__ float g_values[(size_t)BB * HWSZ * DD];   // ~82 MB
__device__ float g_off   [(size_t)BQ * NH * NP * 2]; // ~4.2 MB
__device__ float g_attn  [(size_t)BQ * NH * NP];     // ~2.1 MB
__device__ float g_heads [(size_t)BQ * DD];          // ~17 MB

__device__ __forceinline__ void cp_async16(void* smem_dst, const void* gmem_src) {
    unsigned saddr = (unsigned)__cvta_generic_to_shared(smem_dst);
    asm volatile("cp.async.cg.shared.global [%0], [%1], 16;\n"
                 :: "r"(saddr), "l"(gmem_src) : "memory");
}
__device__ __forceinline__ void cp_async_commit() {
    asm volatile("cp.async.commit_group;\n" ::: "memory");
}
__device__ __forceinline__ void cp_async_wait_all() {
    asm volatile("cp.async.wait_group 0;\n" ::: "memory");
}

// ---------------------------------------------------------------------------
// sgemm128: C[M,N] = A[M,K] @ W[K,N] + bias[N]
// BM=BN=128, BK=16, 256 threads, 8x8 microtile, double-buffered smem.
// A: LDG->reg->STS (transposed into As[k][m]); W: cp.async (contiguous rows).
// Requires: M%128==0, N%128==0, K%16==0.
// ---------------------------------------------------------------------------
__global__ __launch_bounds__(256, 2) void sgemm128_bias(
    const float* __restrict__ A, const float* __restrict__ W,
    const float* __restrict__ bias, float* __restrict__ C,
    int M, int N, int K)
{
    __shared__ float As[2][16][128];   // As[buf][k][m]   16KB each
    __shared__ float Ws[2][16][128];   // Ws[buf][k][n]

    const int t    = threadIdx.x;
    const int row0 = blockIdx.x * 128;
    const int col0 = blockIdx.y * 128;

    // A loader: each thread loads 8 consecutive k (2 float4) of one row.
    const int a_m = t >> 1;            // 0..127
    const int a_k = (t & 1) * 8;       // 0 or 8
    // W loader: one float4 from k-rows w_k and w_k+8.
    const int w_k = t >> 5;            // 0..7
    const int w_n = (t & 31) * 4;      // 0..124

    // compute mapping: 16x16 threads, 8x8 microtile
    const int tx = t & 15;
    const int ty = t >> 4;

    const float* Aptr = A + (size_t)(row0 + a_m) * K + a_k;
    const float* Wptr = W + (size_t)w_k * N + col0 + w_n;
    const size_t wstep8 = (size_t)8 * N;

    float acc[8][8];
    #pragma unroll
    for (int i = 0; i < 8; i++)
        #pragma unroll
        for (int j = 0; j < 8; j++) acc[i][j] = 0.0f;

    // ---- preload tile 0 ----
    cp_async16(&Ws[0][w_k][w_n],     Wptr);
    cp_async16(&Ws[0][w_k + 8][w_n], Wptr + wstep8);
    cp_async_commit();
    {
        const float4 av0 = *reinterpret_cast<const float4*>(Aptr);
        const float4 av1 = *reinterpret_cast<const float4*>(Aptr + 4);
        As[0][a_k + 0][a_m] = av0.x;
        As[0][a_k + 1][a_m] = av0.y;
        As[0][a_k + 2][a_m] = av0.z;
        As[0][a_k + 3][a_m] = av0.w;
        As[0][a_k + 4][a_m] = av1.x;
        As[0][a_k + 5][a_m] = av1.y;
        As[0][a_k + 6][a_m] = av1.z;
        As[0][a_k + 7][a_m] = av1.w;
    }
    cp_async_wait_all();
    __syncthreads();

    int buf = 0;
    for (int k0 = 0; k0 < K; k0 += 16) {
        const bool has_next = (k0 + 16) < K;
        const int nb = buf ^ 1;
        float4 av0, av1;
        if (has_next) {
            // W next tile: straight to smem, no registers held.
            cp_async16(&Ws[nb][w_k][w_n],
                       Wptr + (size_t)(k0 + 16) * N);
            cp_async16(&Ws[nb][w_k + 8][w_n],
                       Wptr + (size_t)(k0 + 24) * N);
            cp_async_commit();
            // A next tile: prefetch to registers (transposed store later).
            av0 = *reinterpret_cast<const float4*>(Aptr + (k0 + 16));
            av1 = *reinterpret_cast<const float4*>(Aptr + (k0 + 20));
        }

        #pragma unroll
        for (int k = 0; k < 16; k++) {
            float a[8], b[8];
            *reinterpret_cast<float4*>(&a[0]) =
                *reinterpret_cast<const float4*>(&As[buf][k][ty * 8]);
            *reinterpret_cast<float4*>(&a[4]) =
                *reinterpret_cast<const float4*>(&As[buf][k][ty * 8 + 4]);
            *reinterpret_cast<float4*>(&b[0]) =
                *reinterpret_cast<const float4*>(&Ws[buf][k][tx * 8]);
            *reinterpret_cast<float4*>(&b[4]) =
                *reinterpret_cast<const float4*>(&Ws[buf][k][tx * 8 + 4]);
            #pragma unroll
            for (int i = 0; i < 8; i++)
                #pragma unroll
                for (int j = 0; j < 8; j++)
                    acc[i][j] = fmaf(a[i], b[j], acc[i][j]);
        }

        if (has_next) {
            As[nb][a_k + 0][a_m] = av0.x;
            As[nb][a_k + 1][a_m] = av0.y;
            As[nb][a_k + 2][a_m] = av0.z;
            As[nb][a_k + 3][a_m] = av0.w;
            As[nb][a_k + 4][a_m] = av1.x;
            As[nb][a_k + 5][a_m] = av1.y;
            As[nb][a_k + 6][a_m] = av1.z;
            As[nb][a_k + 7][a_m] = av1.w;
            cp_async_wait_all();
            __syncthreads();
            buf = nb;
        }
    }

    // epilogue: bias + float4 stores
    float bn[8];
    *reinterpret_cast<float4*>(&bn[0]) =
        *reinterpret_cast<const float4*>(&bias[col0 + tx * 8]);
    *reinterpret_cast<float4*>(&bn[4]) =
        *reinterpret_cast<const float4*>(&bias[col0 + tx * 8 + 4]);

    #pragma unroll
    for (int i = 0; i < 8; i++) {
        const size_t r = (size_t)(row0 + ty * 8 + i);
        float4 o0, o1;
        o0.x = acc[i][0] + bn[0]; o0.y = acc[i][1] + bn[1];
        o0.z = acc[i][2] + bn[2]; o0.w = acc[i][3] + bn[3];
        o1.x = acc[i][4] + bn[4]; o1.y = acc[i][5] + bn[5];
        o1.z = acc[i][6] + bn[6]; o1.w = acc[i][7] + bn[7];
        *reinterpret_cast<float4*>(&C[r * N + col0 + tx * 8])     = o0;
        *reinterpret_cast<float4*>(&C[r * N + col0 + tx * 8 + 4]) = o1;
    }
}

// ---------------------------------------------------------------------------
// gemm64: small-N projections. BM=BN=64, BK=16, 256 threads, 4x4 microtile.
// Requires M%64==0, K%16==0. N may be < 64 (guarded).
// ---------------------------------------------------------------------------
__global__ __launch_bounds__(256) void gemm64_bias(
    const float* __restrict__ A, const float* __restrict__ W,
    const float* __restrict__ bias, float* __restrict__ C,
    int M, int N, int K)
{
    const int BK = 16;
    __shared__ float As[16][64];
    __shared__ float Ws[16][64];

    const int t  = threadIdx.x;
    const int tx = t & 15;
    const int ty = t >> 4;
    const int row0 = blockIdx.x * 64;
    const int col0 = blockIdx.y * 64;

    const int a_m  = t >> 2;
    const int a_k4 = t & 3;
    const int w_k  = t >> 4;
    const int w_n4 = t & 15;

    float acc[4][4];
    #pragma unroll
    for (int i = 0; i < 4; i++)
        #pragma unroll
        for (int j = 0; j < 4; j++) acc[i][j] = 0.0f;

    for (int k0 = 0; k0 < K; k0 += BK) {
        {
            const float4 v = *reinterpret_cast<const float4*>(
                &A[(size_t)(row0 + a_m) * K + k0 + a_k4 * 4]);
            As[a_k4 * 4 + 0][a_m] = v.x;
            As[a_k4 * 4 + 1][a_m] = v.y;
            As[a_k4 * 4 + 2][a_m] = v.z;
            As[a_k4 * 4 + 3][a_m] = v.w;
        }
        {
            const int ncol = col0 + w_n4 * 4;
            float4 v = make_float4(0.f, 0.f, 0.f, 0.f);
            if (ncol < N)
                v = *reinterpret_cast<const float4*>(
                    &W[(size_t)(k0 + w_k) * N + ncol]);
            *reinterpret_cast<float4*>(&Ws[w_k][w_n4 * 4]) = v;
        }
        __syncthreads();

        #pragma unroll
        for (int k = 0; k < BK; k++) {
            const float4 a = *reinterpret_cast<const float4*>(&As[k][ty * 4]);
            const float4 b = *reinterpret_cast<const float4*>(&Ws[k][tx * 4]);
            const float am[4] = {a.x, a.y, a.z, a.w};
            const float bv[4] = {b.x, b.y, b.z, b.w};
            #pragma unroll
            for (int i = 0; i < 4; i++)
                #pragma unroll
                for (int j = 0; j < 4; j++)
                    acc[i][j] = fmaf(am[i], bv[j], acc[i][j]);
        }
        __syncthreads();
    }

    #pragma unroll
    for (int i = 0; i < 4; i++) {
        const int r = row0 + ty * 4 + i;
        #pragma unroll
        for (int j = 0; j < 4; j++) {
            const int c = col0 + tx * 4 + j;
            if (c < N) C[(size_t)r * N + c] = acc[i][j] + bias[c];
        }
    }
}

// ---------------------------------------------------------------------------
// Sampling: one block per (b,q). warp = head, lane = channel within head.
// values layout [b, hw, head, dh] -> each gather is one coalesced 128B line.
// ---------------------------------------------------------------------------
__global__ __launch_bounds__(256) void sample_kernel(
    const float* __restrict__ refp)
{
    const int bq   = blockIdx.x;          // 0..16383
    const int b    = bq / QQ;
    const int head = threadIdx.x >> 5;    // 0..7
    const int lane = threadIdx.x & 31;    // dh

    const float rx = refp[bq * 2 + 0];
    const float ry = refp[bq * 2 + 1];

    // softmax over the 4 points of this head
    float logit[NP];
    #pragma unroll
    for (int p = 0; p < NP; p++)
        logit[p] = g_attn[(size_t)bq * (NH * NP) + head * NP + p];
    float mx = logit[0];
    #pragma unroll
    for (int p = 1; p < NP; p++) mx = fmaxf(mx, logit[p]);
    float wsum = 0.0f, wgt[NP];
    #pragma unroll
    for (int p = 0; p < NP; p++) { wgt[p] = __expf(logit[p] - mx); wsum += wgt[p]; }
    const float inv = 1.0f / wsum;
    #pragma unroll
    for (int p = 0; p < NP; p++) wgt[p] *= inv;

    const float* vbase = g_values + (size_t)b * HWSZ * DD + head * DH + lane;

    float acc = 0.0f;
    #pragma unroll
    for (int p = 0; p < NP; p++) {
        const float ox = g_off[(size_t)bq * (NH * NP * 2) + (head * NP + p) * 2 + 0];
        const float oy = g_off[(size_t)bq * (NH * NP * 2) + (head * NP + p) * 2 + 1];
        const float lx = fminf(fmaxf(rx + ox, 0.0f), 1.0f);
        const float ly = fminf(fmaxf(ry + oy, 0.0f), 1.0f);
        const float sx = lx * (float)(IMW - 1);
        const float sy = ly * (float)(IMH - 1);

        int x0 = (int)floorf(sx);
        int y0 = (int)floorf(sy);
        x0 = min(max(x0, 0), IMW - 1);
        y0 = min(max(y0, 0), IMH - 1);
        const int x1 = min(x0 + 1, IMW - 1);
        const int y1 = min(y0 + 1, IMH - 1);

        const float wx1 = sx - (float)x0;
        const float wx0 = 1.0f - wx1;
        const float wy1 = sy - (float)y0;
        const float wy0 = 1.0f - wy1;

        const float v00 = vbase[(size_t)(y0 * IMW + x0) * DD];
        const float v01 = vbase[(size_t)(y1 * IMW + x0) * DD];
        const float v10 = vbase[(size_t)(y0 * IMW + x1) * DD];
        const float v11 = vbase[(size_t)(y1 * IMW + x1) * DD];

        const float bil = v00 * (wx0 * wy0) + v01 * (wx0 * wy1)
                        + v10 * (wx1 * wy0) + v11 * (wx1 * wy1);
        acc = fmaf(wgt[p], bil, acc);
    }

    g_heads[(size_t)bq * DD + head * DH + lane] = acc;
}

// ---------------------------------------------------------------------------
extern "C" void kernel_launch(void* const* d_in, const int* in_sizes, int n_in,
                              void* d_out, int out_size)
{
    // ---- identify inputs by element count (order-independent, scalar-proof)
    const float *query = 0, *refp = 0, *inpf = 0;
    const float *W_off = 0, *b_off = 0, *W_attn = 0, *b_attn = 0;
    const float *W_val = 0, *b_val = 0, *W_out = 0, *b_out = 0;

    for (int i = 0; i < n_in; i++) {
        const int s = in_sizes[i];
        const float* p = (const float*)d_in[i];
        switch (s) {
            case BB * QQ * DD:        if (!query)  query  = p; break; // 4194304
            case BB * QQ * 2:         if (!refp)   refp   = p; break; // 32768
            case BB * HWSZ * DD:      if (!inpf)   inpf   = p; break; // 20480000
            case DD * NH * NP * 2:    if (!W_off)  W_off  = p; break; // 16384
            case NH * NP * 2:         if (!b_off)  b_off  = p; break; // 64
            case DD * NH * NP:        if (!W_attn) W_attn = p; break; // 8192
            case NH * NP:             if (!b_attn) b_attn = p; break; // 32
            case DD * DD:             if (!W_val)  W_val  = p;        // 65536: val then out
                                      else if (!W_out) W_out = p;     //   (dict order)
                                      break;
            case DD:                  if (!b_val)  b_val  = p;        // 256: val then out
                                      else if (!b_out) b_out = p;
                                      break;
            default: break; // scalars h/w or anything else: ignore
        }
    }
    // Fallback to positional mapping if the size scan didn't resolve.
    if (!query || !refp || !inpf || !W_off || !b_off || !W_attn || !b_attn ||
        !W_val || !b_val || !W_out || !b_out) {
        const int wb = (n_in >= 13) ? 5 : 3;
        query  = (const float*)d_in[0];
        refp   = (const float*)d_in[1];
        inpf   = (const float*)d_in[2];
        W_off  = (const float*)d_in[wb + 0];
        b_off  = (const float*)d_in[wb + 1];
        W_attn = (const float*)d_in[wb + 2];
        b_attn = (const float*)d_in[wb + 3];
        W_val  = (const float*)d_in[wb + 4];
        b_val  = (const float*)d_in[wb + 5];
        W_out  = (const float*)d_in[wb + 6];
        b_out  = (const float*)d_in[wb + 7];
    }
    float* out = (float*)d_out;

    float *p_values, *p_off, *p_attn, *p_heads;
    cudaGetSymbolAddress((void**)&p_values, g_values);
    cudaGetSymbolAddress((void**)&p_off,    g_off);
    cudaGetSymbolAddress((void**)&p_attn,   g_attn);
    cudaGetSymbolAddress((void**)&p_heads,  g_heads);

    // 1) value projection: [80000,256]  (80000 % 128 == 0)
    {
        dim3 grid((BB * HWSZ) / 128, DD / 128);
        sgemm128_bias<<<grid, 256>>>(inpf, W_val, b_val, p_values,
                                     BB * HWSZ, DD, DD);
    }
    // 2) offset projection: [16384,64]
    {
        dim3 grid(BQ / 64, 1);
        gemm64_bias<<<grid, 256>>>(query, W_off, b_off, p_off,
                                   BQ, NH * NP * 2, DD);
    }
    // 3) attention projection: [16384,32]
    {
        dim3 grid(BQ / 64, 1);
        gemm64_bias<<<grid, 256>>>(query, W_attn, b_attn, p_attn,
                                   BQ, NH * NP, DD);
    }
    // 4) sampling + weighted sum -> g_heads [16384,256]
    sample_kernel<<<BQ, 256>>>(refp);

    // 5) output projection: [16384,256]
    {
        dim3 grid(BQ / 128, DD / 128);
        sgemm128_bias<<<grid, 256>>>(p_heads, W_out, b_out, out,
                                     BQ, DD, DD);
    }
}

// round 12
// speedup vs baseline: 1.4405x; 1.4405x over previous
#include <cuda_runtime.h>
#include <cuda_bf16.h>
#include <math.h>
#include <stdint.h>

// ---------------------------------------------------------------------------
// DeformableAttention — big GEMMs on tensor cores via bf16 split-precision
// (hi+lo, 3x mma.sync m16n8k16, fp32 accum; error ~2^-16), small projections
// and sampling unchanged from the 394us fp32 baseline.
//   B=8, Q=2048, D=256, HW=100*100, heads=8, points=4, Dh=32
// ---------------------------------------------------------------------------

#define NH   8
#define NP   4
#define DH   32
#define DD   256
#define BB   8
#define QQ   2048
#define IMH  100
#define IMW  100
#define HWSZ (IMH * IMW)
#define BQ   (BB * QQ)

__device__ float g_values[(size_t)BB * HWSZ * DD];   // ~82 MB
__device__ float g_off   [(size_t)BQ * NH * NP * 2]; // ~4.2 MB
__device__ float g_attn  [(size_t)BQ * NH * NP];     // ~2.1 MB
__device__ float g_heads [(size_t)BQ * DD];          // ~17 MB

__device__ __forceinline__ uint32_t smem_u32(const void* p) {
    return (uint32_t)__cvta_generic_to_shared(p);
}

__device__ __forceinline__ void ldsm_x4(uint32_t* r, uint32_t addr) {
    asm volatile("ldmatrix.sync.aligned.m8n8.x4.shared.b16 {%0,%1,%2,%3}, [%4];"
                 : "=r"(r[0]), "=r"(r[1]), "=r"(r[2]), "=r"(r[3]) : "r"(addr));
}
__device__ __forceinline__ void ldsm_x4t(uint32_t* r, uint32_t addr) {
    asm volatile("ldmatrix.sync.aligned.m8n8.x4.trans.shared.b16 {%0,%1,%2,%3}, [%4];"
                 : "=r"(r[0]), "=r"(r[1]), "=r"(r[2]), "=r"(r[3]) : "r"(addr));
}
__device__ __forceinline__ void mma_bf16(float* d, const uint32_t* a, const uint32_t* b) {
    asm volatile(
        "mma.sync.aligned.m16n8k16.row.col.f32.bf16.bf16.f32 "
        "{%0,%1,%2,%3}, {%4,%5,%6,%7}, {%8,%9}, {%0,%1,%2,%3};"
        : "+f"(d[0]), "+f"(d[1]), "+f"(d[2]), "+f"(d[3])
        : "r"(a[0]), "r"(a[1]), "r"(a[2]), "r"(a[3]), "r"(b[0]), "r"(b[1]));
}

// ---------------------------------------------------------------------------
// gemm_bf16x3: C[M,N] = A[M,K] @ W[K,N] + bias  via bf16 hi/lo split MMA.
// BM=BN=128, BK=32. 8 warps as 4(m) x 2(n); warp tile 32x64.
// Requires: M%128==0, N%128==0, K%32==0.
// ---------------------------------------------------------------------------
#define LDA 40    // bf16 per A smem row (padded: 80B row stride, ldsm conflict-free)
#define LDB 136   // bf16 per B smem row (272B row stride, ldsm conflict-free)

__global__ __launch_bounds__(256, 2) void gemm_bf16x3_bias(
    const float* __restrict__ A, const float* __restrict__ W,
    const float* __restrict__ bias, float* __restrict__ C,
    int M, int N, int K)
{
    __shared__ __nv_bfloat16 As_hi[128 * LDA];
    __shared__ __nv_bfloat16 As_lo[128 * LDA];
    __shared__ __nv_bfloat16 Bs_hi[32 * LDB];
    __shared__ __nv_bfloat16 Bs_lo[32 * LDB];

    const int t      = threadIdx.x;
    const int lane   = t & 31;
    const int wid    = t >> 5;
    const int warp_m = wid >> 1;          // 0..3 -> 32 rows each
    const int warp_n = wid & 1;           // 0..1 -> 64 cols each
    const int row0   = blockIdx.x * 128;
    const int col0   = blockIdx.y * 128;

    // loader mappings
    const int a_r = t >> 1;               // 0..127
    const int a_c = (t & 1) * 16;         // 0 / 16   (16 floats each)
    const int b_r = t >> 3;               // 0..31
    const int b_c = (t & 7) * 16;         // 0..112   (16 floats each)

    float acc[2][8][4];
    #pragma unroll
    for (int mt = 0; mt < 2; mt++)
        #pragma unroll
        for (int nt = 0; nt < 8; nt++)
            #pragma unroll
            for (int q = 0; q < 4; q++) acc[mt][nt][q] = 0.0f;

    for (int kt = 0; kt < K; kt += 32) {
        if (kt) __syncthreads();   // previous mma reads done before overwrite

        // ---- load + split-convert A tile [128 x 32] ----
        {
            const float* ap = A + (size_t)(row0 + a_r) * K + kt + a_c;
            float xs[16];
            #pragma unroll
            for (int q = 0; q < 4; q++)
                *reinterpret_cast<float4*>(xs + 4 * q) =
                    reinterpret_cast<const float4*>(ap)[q];
            uint32_t* dh = reinterpret_cast<uint32_t*>(As_hi + a_r * LDA + a_c);
            uint32_t* dl = reinterpret_cast<uint32_t*>(As_lo + a_r * LDA + a_c);
            #pragma unroll
            for (int p = 0; p < 8; p++) {
                const float x0 = xs[2 * p], x1 = xs[2 * p + 1];
                const __nv_bfloat16 h0 = __float2bfloat16(x0);
                const __nv_bfloat16 h1 = __float2bfloat16(x1);
                const __nv_bfloat16 g0 = __float2bfloat16(x0 - __bfloat162float(h0));
                const __nv_bfloat16 g1 = __float2bfloat16(x1 - __bfloat162float(h1));
                dh[p] = (uint32_t)__bfloat16_as_ushort(h0)
                      | ((uint32_t)__bfloat16_as_ushort(h1) << 16);
                dl[p] = (uint32_t)__bfloat16_as_ushort(g0)
                      | ((uint32_t)__bfloat16_as_ushort(g1) << 16);
            }
        }
        // ---- load + split-convert W tile [32 x 128] ----
        {
            const float* wp = W + (size_t)(kt + b_r) * N + col0 + b_c;
            float xs[16];
            #pragma unroll
            for (int q = 0; q < 4; q++)
                *reinterpret_cast<float4*>(xs + 4 * q) =
                    reinterpret_cast<const float4*>(wp)[q];
            uint32_t* dh = reinterpret_cast<uint32_t*>(Bs_hi + b_r * LDB + b_c);
            uint32_t* dl = reinterpret_cast<uint32_t*>(Bs_lo + b_r * LDB + b_c);
            #pragma unroll
            for (int p = 0; p < 8; p++) {
                const float x0 = xs[2 * p], x1 = xs[2 * p + 1];
                const __nv_bfloat16 h0 = __float2bfloat16(x0);
                const __nv_bfloat16 h1 = __float2bfloat16(x1);
                const __nv_bfloat16 g0 = __float2bfloat16(x0 - __bfloat162float(h0));
                const __nv_bfloat16 g1 = __float2bfloat16(x1 - __bfloat162float(h1));
                dh[p] = (uint32_t)__bfloat16_as_ushort(h0)
                      | ((uint32_t)__bfloat16_as_ushort(h1) << 16);
                dl[p] = (uint32_t)__bfloat16_as_ushort(g0)
                      | ((uint32_t)__bfloat16_as_ushort(g1) << 16);
            }
        }
        __syncthreads();

        // ---- two k16 steps of MMA ----
        #pragma unroll
        for (int ks = 0; ks < 2; ks++) {
            uint32_t ahi[2][4], alo[2][4];
            #pragma unroll
            for (int mt = 0; mt < 2; mt++) {
                const int r = warp_m * 32 + mt * 16 + (lane & 15);
                const int c = ks * 16 + (lane >> 4) * 8;
                ldsm_x4(ahi[mt], smem_u32(As_hi + r * LDA + c));
                ldsm_x4(alo[mt], smem_u32(As_lo + r * LDA + c));
            }
            #pragma unroll
            for (int g = 0; g < 4; g++) {
                const int kr = ks * 16 + (lane & 15);
                const int nc = warp_n * 64 + g * 16 + (lane >> 4) * 8;
                uint32_t bhi[4], blo[4];
                ldsm_x4t(bhi, smem_u32(Bs_hi + kr * LDB + nc));
                ldsm_x4t(blo, smem_u32(Bs_lo + kr * LDB + nc));
                #pragma unroll
                for (int mt = 0; mt < 2; mt++) {
                    #pragma unroll
                    for (int h = 0; h < 2; h++) {
                        float* d = acc[mt][g * 2 + h];
                        mma_bf16(d, ahi[mt], &bhi[h * 2]);  // hi*hi
                        mma_bf16(d, ahi[mt], &blo[h * 2]);  // hi*lo
                        mma_bf16(d, alo[mt], &bhi[h * 2]);  // lo*hi
                    }
                }
            }
        }
    }

    // ---- epilogue: bias + stores ----
    const int tr = lane >> 2;          // 0..7
    const int tc = (lane & 3) * 2;     // 0,2,4,6
    #pragma unroll
    for (int mt = 0; mt < 2; mt++) {
        #pragma unroll
        for (int nt = 0; nt < 8; nt++) {
            const int r = row0 + warp_m * 32 + mt * 16 + tr;
            const int c = col0 + warp_n * 64 + nt * 8 + tc;
            const float b0 = bias[c], b1 = bias[c + 1];
            float2 v0 = make_float2(acc[mt][nt][0] + b0, acc[mt][nt][1] + b1);
            float2 v1 = make_float2(acc[mt][nt][2] + b0, acc[mt][nt][3] + b1);
            *reinterpret_cast<float2*>(&C[(size_t)r * N + c])       = v0;
            *reinterpret_cast<float2*>(&C[(size_t)(r + 8) * N + c]) = v1;
        }
    }
}

// ---------------------------------------------------------------------------
// gemm64: small-N projections (unchanged, proven).
// ---------------------------------------------------------------------------
__global__ __launch_bounds__(256) void gemm64_bias(
    const float* __restrict__ A, const float* __restrict__ W,
    const float* __restrict__ bias, float* __restrict__ C,
    int M, int N, int K)
{
    const int BK = 16;
    __shared__ float As[16][64];
    __shared__ float Ws[16][64];

    const int t  = threadIdx.x;
    const int tx = t & 15;
    const int ty = t >> 4;
    const int row0 = blockIdx.x * 64;
    const int col0 = blockIdx.y * 64;

    const int a_m  = t >> 2;
    const int a_k4 = t & 3;
    const int w_k  = t >> 4;
    const int w_n4 = t & 15;

    float acc[4][4];
    #pragma unroll
    for (int i = 0; i < 4; i++)
        #pragma unroll
        for (int j = 0; j < 4; j++) acc[i][j] = 0.0f;

    for (int k0 = 0; k0 < K; k0 += BK) {
        {
            const float4 v = *reinterpret_cast<const float4*>(
                &A[(size_t)(row0 + a_m) * K + k0 + a_k4 * 4]);
            As[a_k4 * 4 + 0][a_m] = v.x;
            As[a_k4 * 4 + 1][a_m] = v.y;
            As[a_k4 * 4 + 2][a_m] = v.z;
            As[a_k4 * 4 + 3][a_m] = v.w;
        }
        {
            const int ncol = col0 + w_n4 * 4;
            float4 v = make_float4(0.f, 0.f, 0.f, 0.f);
            if (ncol < N)
                v = *reinterpret_cast<const float4*>(
                    &W[(size_t)(k0 + w_k) * N + ncol]);
            *reinterpret_cast<float4*>(&Ws[w_k][w_n4 * 4]) = v;
        }
        __syncthreads();

        #pragma unroll
        for (int k = 0; k < BK; k++) {
            const float4 a = *reinterpret_cast<const float4*>(&As[k][ty * 4]);
            const float4 b = *reinterpret_cast<const float4*>(&Ws[k][tx * 4]);
            const float am[4] = {a.x, a.y, a.z, a.w};
            const float bv[4] = {b.x, b.y, b.z, b.w};
            #pragma unroll
            for (int i = 0; i < 4; i++)
                #pragma unroll
                for (int j = 0; j < 4; j++)
                    acc[i][j] = fmaf(am[i], bv[j], acc[i][j]);
        }
        __syncthreads();
    }

    #pragma unroll
    for (int i = 0; i < 4; i++) {
        const int r = row0 + ty * 4 + i;
        #pragma unroll
        for (int j = 0; j < 4; j++) {
            const int c = col0 + tx * 4 + j;
            if (c < N) C[(size_t)r * N + c] = acc[i][j] + bias[c];
        }
    }
}

// ---------------------------------------------------------------------------
// Sampling (unchanged, measured 49.4us).
// ---------------------------------------------------------------------------
__global__ __launch_bounds__(256) void sample_kernel(
    const float* __restrict__ refp)
{
    const int bq   = blockIdx.x;
    const int b    = bq / QQ;
    const int head = threadIdx.x >> 5;
    const int lane = threadIdx.x & 31;

    const float rx = refp[bq * 2 + 0];
    const float ry = refp[bq * 2 + 1];

    float logit[NP];
    #pragma unroll
    for (int p = 0; p < NP; p++)
        logit[p] = g_attn[(size_t)bq * (NH * NP) + head * NP + p];
    float mx = logit[0];
    #pragma unroll
    for (int p = 1; p < NP; p++) mx = fmaxf(mx, logit[p]);
    float wsum = 0.0f, wgt[NP];
    #pragma unroll
    for (int p = 0; p < NP; p++) { wgt[p] = __expf(logit[p] - mx); wsum += wgt[p]; }
    const float inv = 1.0f / wsum;
    #pragma unroll
    for (int p = 0; p < NP; p++) wgt[p] *= inv;

    const float* vbase = g_values + (size_t)b * HWSZ * DD + head * DH + lane;

    float acc = 0.0f;
    #pragma unroll
    for (int p = 0; p < NP; p++) {
        const float ox = g_off[(size_t)bq * (NH * NP * 2) + (head * NP + p) * 2 + 0];
        const float oy = g_off[(size_t)bq * (NH * NP * 2) + (head * NP + p) * 2 + 1];
        const float lx = fminf(fmaxf(rx + ox, 0.0f), 1.0f);
        const float ly = fminf(fmaxf(ry + oy, 0.0f), 1.0f);
        const float sx = lx * (float)(IMW - 1);
        const float sy = ly * (float)(IMH - 1);

        int x0 = (int)floorf(sx);
        int y0 = (int)floorf(sy);
        x0 = min(max(x0, 0), IMW - 1);
        y0 = min(max(y0, 0), IMH - 1);
        const int x1 = min(x0 + 1, IMW - 1);
        const int y1 = min(y0 + 1, IMH - 1);

        const float wx1 = sx - (float)x0;
        const float wx0 = 1.0f - wx1;
        const float wy1 = sy - (float)y0;
        const float wy0 = 1.0f - wy1;

        const float v00 = vbase[(size_t)(y0 * IMW + x0) * DD];
        const float v01 = vbase[(size_t)(y1 * IMW + x0) * DD];
        const float v10 = vbase[(size_t)(y0 * IMW + x1) * DD];
        const float v11 = vbase[(size_t)(y1 * IMW + x1) * DD];

        const float bil = v00 * (wx0 * wy0) + v01 * (wx0 * wy1)
                        + v10 * (wx1 * wy0) + v11 * (wx1 * wy1);
        acc = fmaf(wgt[p], bil, acc);
    }

    g_heads[(size_t)bq * DD + head * DH + lane] = acc;
}

// ---------------------------------------------------------------------------
extern "C" void kernel_launch(void* const* d_in, const int* in_sizes, int n_in,
                              void* d_out, int out_size)
{
    // ---- identify inputs by element count (order-independent, scalar-proof)
    const float *query = 0, *refp = 0, *inpf = 0;
    const float *W_off = 0, *b_off = 0, *W_attn = 0, *b_attn = 0;
    const float *W_val = 0, *b_val = 0, *W_out = 0, *b_out = 0;

    for (int i = 0; i < n_in; i++) {
        const int s = in_sizes[i];
        const float* p = (const float*)d_in[i];
        switch (s) {
            case BB * QQ * DD:        if (!query)  query  = p; break;
            case BB * QQ * 2:         if (!refp)   refp   = p; break;
            case BB * HWSZ * DD:      if (!inpf)   inpf   = p; break;
            case DD * NH * NP * 2:    if (!W_off)  W_off  = p; break;
            case NH * NP * 2:         if (!b_off)  b_off  = p; break;
            case DD * NH * NP:        if (!W_attn) W_attn = p; break;
            case NH * NP:             if (!b_attn) b_attn = p; break;
            case DD * DD:             if (!W_val)  W_val  = p;
                                      else if (!W_out) W_out = p;
                                      break;
            case DD:                  if (!b_val)  b_val  = p;
                                      else if (!b_out) b_out = p;
                                      break;
            default: break;
        }
    }
    if (!query || !refp || !inpf || !W_off || !b_off || !W_attn || !b_attn ||
        !W_val || !b_val || !W_out || !b_out) {
        const int wb = (n_in >= 13) ? 5 : 3;
        query  = (const float*)d_in[0];
        refp   = (const float*)d_in[1];
        inpf   = (const float*)d_in[2];
        W_off  = (const float*)d_in[wb + 0];
        b_off  = (const float*)d_in[wb + 1];
        W_attn = (const float*)d_in[wb + 2];
        b_attn = (const float*)d_in[wb + 3];
        W_val  = (const float*)d_in[wb + 4];
        b_val  = (const float*)d_in[wb + 5];
        W_out  = (const float*)d_in[wb + 6];
        b_out  = (const float*)d_in[wb + 7];
    }
    float* out = (float*)d_out;

    float *p_values, *p_off, *p_attn, *p_heads;
    cudaGetSymbolAddress((void**)&p_values, g_values);
    cudaGetSymbolAddress((void**)&p_off,    g_off);
    cudaGetSymbolAddress((void**)&p_attn,   g_attn);
    cudaGetSymbolAddress((void**)&p_heads,  g_heads);

    // 1) value projection: [80000,256] (tensor cores, bf16 split)
    {
        dim3 grid((BB * HWSZ) / 128, DD / 128);
        gemm_bf16x3_bias<<<grid, 256>>>(inpf, W_val, b_val, p_values,
                                        BB * HWSZ, DD, DD);
    }
    // 2) offset projection: [16384,64]
    {
        dim3 grid(BQ / 64, 1);
        gemm64_bias<<<grid, 256>>>(query, W_off, b_off, p_off,
                                   BQ, NH * NP * 2, DD);
    }
    // 3) attention projection: [16384,32]
    {
        dim3 grid(BQ / 64, 1);
        gemm64_bias<<<grid, 256>>>(query, W_attn, b_attn, p_attn,
                                   BQ, NH * NP, DD);
    }
    // 4) sampling + weighted sum -> g_heads [16384,256]
    sample_kernel<<<BQ, 256>>>(refp);

    // 5) output projection: [16384,256] (tensor cores, bf16 split)
    {
        dim3 grid(BQ / 128, DD / 128);
        gemm_bf16x3_bias<<<grid, 256>>>(p_heads, W_out, b_out, out,
                                        BQ, DD, DD);
    }
}